// round 5
// baseline (speedup 1.0000x reference)
#include <cuda_runtime.h>
#include <cuda_bf16.h>
#include <cstdint>

#define HW 4096
#define CC 256
#define BB 4

// ---- scratch (static device arrays; no allocation allowed) ----
__device__ __align__(16) __nv_bfloat16 g_h [BB*CC*HW];   // groupnorm out, (b, c, s)
__device__ __align__(16) __nv_bfloat16 g_q [BB*CC*HW];   // q (b, c, s), pre-scaled by C^-0.5
__device__ __align__(16) __nv_bfloat16 g_kt[BB*HW*CC];   // k transposed: (b, m, c)
__device__ __align__(16) __nv_bfloat16 g_v [BB*CC*HW];   // v (b, c, s)
__device__ __align__(16) __nv_bfloat16 g_a [BB*HW*CC];   // attention out, (b, n, c)
__device__ __align__(16) __nv_bfloat16 g_wq[CC*CC], g_wk[CC*CC], g_wv[CC*CC], g_wp[CC*CC];

// ============================================================
// Weight conversion fp32 -> bf16 (once per launch, tiny)
// ============================================================
__global__ void wconv_kernel(const float* __restrict__ wq, const float* __restrict__ wk,
                             const float* __restrict__ wv, const float* __restrict__ wp) {
    int i = blockIdx.x * 256 + threadIdx.x;   // 65536 threads
    g_wq[i] = __float2bfloat16(wq[i]);
    g_wk[i] = __float2bfloat16(wk[i]);
    g_wv[i] = __float2bfloat16(wv[i]);
    g_wp[i] = __float2bfloat16(wp[i]);
}

// ============================================================
// GroupNorm: one block per (batch, group). bf16 output.
// ============================================================
__global__ void gn_kernel(const float* __restrict__ x,
                          const float* __restrict__ gw,
                          const float* __restrict__ gb) {
    int b = blockIdx.x >> 5;
    int g = blockIdx.x & 31;
    const float* xp = x   + ((size_t)b*CC + g*8) * HW;
    __nv_bfloat16* hp = g_h + ((size_t)b*CC + g*8) * HW;
    int tid = threadIdx.x;

    float s = 0.f, ss = 0.f;
    for (int i = tid; i < 8*HW; i += 256) {
        float v = xp[i];
        s += v; ss += v*v;
    }
    __shared__ float red0[8], red1[8];
    #pragma unroll
    for (int off = 16; off; off >>= 1) {
        s  += __shfl_xor_sync(0xffffffffu, s,  off);
        ss += __shfl_xor_sync(0xffffffffu, ss, off);
    }
    if ((tid & 31) == 0) { red0[tid>>5] = s; red1[tid>>5] = ss; }
    __syncthreads();
    __shared__ float mu_s, rstd_s;
    if (tid == 0) {
        float S = 0.f, SS = 0.f;
        #pragma unroll
        for (int i = 0; i < 8; i++) { S += red0[i]; SS += red1[i]; }
        float inv = 1.0f / (8.0f*HW);
        float mu = S * inv;
        float var = SS * inv - mu*mu;
        mu_s = mu;
        rstd_s = rsqrtf(var + 1e-5f);
    }
    __syncthreads();
    float mu = mu_s, rstd = rstd_s;
    for (int i = tid*2; i < 8*HW; i += 512) {
        int c = g*8 + (i >> 12);
        float a = gw[c]*rstd, bb2 = gb[c] - mu*a;
        float2 v = *reinterpret_cast<const float2*>(&xp[i]);
        __nv_bfloat162 r = __floats2bfloat162_rn(v.x*a + bb2, v.y*a + bb2);
        *reinterpret_cast<__nv_bfloat162*>(&hp[i]) = r;
    }
}

// ============================================================
// mma helpers
// ============================================================
__device__ __forceinline__ uint32_t s2u(const void* p) {
    uint32_t a;
    asm("{ .reg .u64 t; cvta.to.shared.u64 t, %1; cvt.u32.u64 %0, t; }" : "=r"(a) : "l"(p));
    return a;
}
__device__ __forceinline__ void ldm4(uint32_t& r0, uint32_t& r1, uint32_t& r2, uint32_t& r3, uint32_t a) {
    asm volatile("ldmatrix.sync.aligned.m8n8.x4.shared.b16 {%0,%1,%2,%3},[%4];"
                 : "=r"(r0), "=r"(r1), "=r"(r2), "=r"(r3) : "r"(a));
}
__device__ __forceinline__ void ldm4t(uint32_t& r0, uint32_t& r1, uint32_t& r2, uint32_t& r3, uint32_t a) {
    asm volatile("ldmatrix.sync.aligned.m8n8.x4.trans.shared.b16 {%0,%1,%2,%3},[%4];"
                 : "=r"(r0), "=r"(r1), "=r"(r2), "=r"(r3) : "r"(a));
}
__device__ __forceinline__ void mma16816(float* d, uint32_t a0, uint32_t a1, uint32_t a2, uint32_t a3,
                                         uint32_t b0, uint32_t b1) {
    asm volatile("mma.sync.aligned.m16n8k16.row.col.f32.bf16.bf16.f32 "
                 "{%0,%1,%2,%3},{%4,%5,%6,%7},{%8,%9},{%0,%1,%2,%3};"
                 : "+f"(d[0]), "+f"(d[1]), "+f"(d[2]), "+f"(d[3])
                 : "r"(a0), "r"(a1), "r"(a2), "r"(a3), "r"(b0), "r"(b1));
}
__device__ __forceinline__ uint32_t cvt2(float hi, float lo) {
    uint32_t d; asm("cvt.rn.bf16x2.f32 %0, %1, %2;" : "=r"(d) : "f"(hi), "f"(lo)); return d;
}
__device__ __forceinline__ void cpa16(uint32_t dst, const void* src) {
    asm volatile("cp.async.cg.shared.global [%0], [%1], 16;" :: "r"(dst), "l"(src));
}

// ============================================================
// 1x1 conv projections, bf16 tensor-core GEMM, full K=256 in smem.
// MODE 0: q  out[o,s]  (scaled 1/16)    M=o(64) N=s(128)
// MODE 1: kt out[s,o]                    M=s(128) N=o(64)
// MODE 2: v  out[o,s]                    M=o(64) N=s(128)
// grid: (32 s-blocks, 4 o-blocks, batch)
// ============================================================
#define HSTR 136   // H smem: 256 k-rows x 128 s-cols (+pad)
#define WSTR 264   // W smem: 64 o-rows x 256 k-cols (+pad)

template<int MODE>
__global__ void __launch_bounds__(256) proj_tc_kernel(const float* __restrict__ bias) {
    int b  = blockIdx.z;
    int s0 = blockIdx.x << 7;
    int o0 = blockIdx.y << 6;
    const __nv_bfloat16* Hb = g_h + (size_t)b*CC*HW;
    const __nv_bfloat16* Wb = (MODE == 0) ? g_wq : (MODE == 1) ? g_wk : g_wv;

    extern __shared__ __nv_bfloat16 smp[];
    __nv_bfloat16* Hs = smp;              // 256 x HSTR
    __nv_bfloat16* Ws = smp + 256*HSTR;   // 64 x WSTR

    int tid = threadIdx.x, lane = tid & 31, warp = tid >> 5;
    int l8 = lane & 7;

    // load H strip (256 x 128) and W block (64 x 256)
    for (int l = tid; l < 4096; l += 256) {
        int row = l >> 4, col = (l & 15) << 3;
        *reinterpret_cast<uint4*>(&Hs[row*HSTR + col]) =
            *reinterpret_cast<const uint4*>(&Hb[(size_t)row*HW + s0 + col]);
    }
    for (int l = tid; l < 2048; l += 256) {
        int row = l >> 5, col = (l & 31) << 3;
        *reinterpret_cast<uint4*>(&Ws[row*WSTR + col]) =
            *reinterpret_cast<const uint4*>(&Wb[(o0+row)*CC + col]);
    }
    __syncthreads();

    uint32_t Hsa = s2u(Hs), Wsa = s2u(Ws);
    float acc[8][4];
    #pragma unroll
    for (int j = 0; j < 8; j++) { acc[j][0]=acc[j][1]=acc[j][2]=acc[j][3]=0.f; }

    if (MODE != 1) {
        // M=o: A=W (non-trans), B=H (trans). warp: 16o x 64s
        int warp_o = warp >> 1, warp_s = warp & 1;
        uint32_t a_base = Wsa + (uint32_t)((warp_o*16 + l8 + ((lane>>3)&1)*8)*WSTR + (lane>>4)*8) * 2;
        uint32_t b_base = Hsa + (uint32_t)((l8 + ((lane>>3)&1)*8)*HSTR + warp_s*64 + (lane>>4)*8) * 2;
        #pragma unroll 4
        for (int kk = 0; kk < 16; kk++) {
            uint32_t a0,a1,a2,a3;
            ldm4(a0,a1,a2,a3, a_base + kk*32);
            #pragma unroll
            for (int g = 0; g < 4; g++) {
                uint32_t b00,b01,b10,b11;
                ldm4t(b00,b01,b10,b11, b_base + (uint32_t)(kk*16*HSTR + g*16)*2);
                mma16816(acc[2*g],   a0,a1,a2,a3, b00,b01);
                mma16816(acc[2*g+1], a0,a1,a2,a3, b10,b11);
            }
        }
        // epilogue: out[o, s]
        const float scale = (MODE == 0) ? 0.0625f : 1.0f;
        __nv_bfloat16* ob = (MODE == 0 ? g_q : g_v) + (size_t)b*CC*HW;
        int qr = lane >> 2, qc = (lane & 3) << 1;
        #pragma unroll
        for (int h = 0; h < 2; h++) {
            int o_r = o0 + warp_o*16 + qr + 8*h;
            float bv = bias[o_r];
            #pragma unroll
            for (int j = 0; j < 8; j++) {
                int s_c = s0 + warp_s*64 + j*8 + qc;
                uint32_t r = cvt2((acc[j][2*h+1]+bv)*scale, (acc[j][2*h]+bv)*scale);
                *reinterpret_cast<uint32_t*>(&ob[(size_t)o_r*HW + s_c]) = r;
            }
        }
    } else {
        // M=s: A=H (trans-A), B=W (non-trans). warp: 16s x 64o
        uint32_t a_base = Hsa + (uint32_t)((l8 + ((lane>>4)&1)*8)*HSTR + warp*16 + ((lane>>3)&1)*8) * 2;
        uint32_t b_base = Wsa + (uint32_t)((((lane>>4)&1)*8 + l8)*WSTR + ((lane>>3)&1)*8) * 2;
        #pragma unroll 4
        for (int kk = 0; kk < 16; kk++) {
            uint32_t a0,a1,a2,a3;
            ldm4t(a0,a1,a2,a3, a_base + (uint32_t)(kk*16*HSTR)*2);
            #pragma unroll
            for (int g = 0; g < 4; g++) {
                uint32_t b00,b01,b10,b11;
                ldm4(b00,b01,b10,b11, b_base + (uint32_t)(g*16*WSTR)*2 + kk*32);
                mma16816(acc[2*g],   a0,a1,a2,a3, b00,b01);
                mma16816(acc[2*g+1], a0,a1,a2,a3, b10,b11);
            }
        }
        // epilogue: out[s, o]
        __nv_bfloat16* ob = g_kt + (size_t)b*HW*CC;
        int qr = lane >> 2, qc = (lane & 3) << 1;
        #pragma unroll
        for (int h = 0; h < 2; h++) {
            int s_r = s0 + warp*16 + qr + 8*h;
            #pragma unroll
            for (int j = 0; j < 8; j++) {
                int o_c = o0 + j*8 + qc;
                uint32_t r = cvt2(acc[j][2*h+1]+bias[o_c+1], acc[j][2*h]+bias[o_c]);
                *reinterpret_cast<uint32_t*>(&ob[(size_t)s_r*CC + o_c]) = r;
            }
        }
    }
}

// ============================================================
// Flash attention, bf16 mma.sync, cp.async double-buffered K/V.
// 256 threads = 8 warps. Br=128, Bc=64, d=256.
// ============================================================
#define ASTR 264

__global__ void __launch_bounds__(256, 1) attn_kernel() {
    int b  = blockIdx.y;
    int n0 = blockIdx.x << 7;
    const __nv_bfloat16* qf = g_q  + (size_t)b*CC*HW;
    const __nv_bfloat16* kf = g_kt + (size_t)b*HW*CC;
    const __nv_bfloat16* vf = g_v  + (size_t)b*CC*HW;

    extern __shared__ __nv_bfloat16 sm[];
    __nv_bfloat16* Qs = sm;                         // 128 x ASTR
    __nv_bfloat16* Kb[2] = { Qs + 128*ASTR, Qs + 192*ASTR };
    __nv_bfloat16* Vb[2] = { Qs + 256*ASTR, Qs + 320*ASTR };

    int tid  = threadIdx.x;
    int lane = tid & 31, warp = tid >> 5;
    int r0 = warp << 4;
    int l8 = lane & 7;

    // load Q tile
    {
        const uint4* src = reinterpret_cast<const uint4*>(qf + (size_t)n0*CC);
        for (int l = tid; l < 4096; l += 256) {
            int row = l >> 5, col = (l & 31) << 3;
            *reinterpret_cast<uint4*>(&Qs[row*ASTR + col]) = src[l];
        }
    }

    // prefetch tile 0 via cp.async
    {
        uint32_t Kd = s2u(Kb[0]), Vd = s2u(Vb[0]);
        const uint4* ks = reinterpret_cast<const uint4*>(kf);
        const uint4* vs = reinterpret_cast<const uint4*>(vf);
        for (int l = tid; l < 2048; l += 256) {
            int row = l >> 5; uint32_t off = ((row*ASTR) + ((l & 31) << 3)) * 2;
            cpa16(Kd + off, &ks[l]);
            cpa16(Vd + off, &vs[l]);
        }
        asm volatile("cp.async.commit_group;");
    }

    uint32_t Qsa = s2u(Qs);
    uint32_t a_base = Qsa + ((r0 + l8 + ((lane >> 3) & 1)*8)*ASTR + (lane >> 4)*8) * 2;
    uint32_t kb_pat = (uint32_t)((((lane >> 4) & 1)*8 + l8)*ASTR + ((lane >> 3) & 1)*8) * 2;
    uint32_t vb_pat = (uint32_t)((((lane >> 3) & 1)*8 + l8)*ASTR + (lane >> 4)*8) * 2;

    float s[8][4];
    float o[32][4];
    #pragma unroll
    for (int j = 0; j < 32; j++) { o[j][0]=o[j][1]=o[j][2]=o[j][3]=0.f; }
    float mrow[2] = {-1e30f, -1e30f};
    float lrow[2] = {0.f, 0.f};

    for (int t = 0; t < 64; t++) {
        // prefetch next tile into other buffer (safe: prev compute on it done + barrier)
        if (t + 1 < 64) {
            int nb = (t + 1) & 1;
            uint32_t Kd = s2u(Kb[nb]), Vd = s2u(Vb[nb]);
            const uint4* ks = reinterpret_cast<const uint4*>(kf + (size_t)(t+1)*64*CC);
            const uint4* vs = reinterpret_cast<const uint4*>(vf + (size_t)(t+1)*64*CC);
            for (int l = tid; l < 2048; l += 256) {
                int row = l >> 5; uint32_t off = ((row*ASTR) + ((l & 31) << 3)) * 2;
                cpa16(Kd + off, &ks[l]);
                cpa16(Vd + off, &vs[l]);
            }
            asm volatile("cp.async.commit_group;");
            asm volatile("cp.async.wait_group 1;");
        } else {
            asm volatile("cp.async.wait_group 0;");
        }
        __syncthreads();

        uint32_t Ksa = s2u(Kb[t & 1]), Vsa = s2u(Vb[t & 1]);
        uint32_t kb_base = Ksa + kb_pat;
        uint32_t vb_base = Vsa + vb_pat;

        // ---- S = Q @ K^T ----
        #pragma unroll
        for (int j = 0; j < 8; j++) { s[j][0]=s[j][1]=s[j][2]=s[j][3]=0.f; }
        #pragma unroll 4
        for (int kk = 0; kk < 16; kk++) {
            uint32_t a0,a1,a2,a3;
            ldm4(a0,a1,a2,a3, a_base + kk*32);
            #pragma unroll
            for (int g = 0; g < 4; g++) {
                uint32_t b00,b01,b10,b11;
                ldm4(b00,b01,b10,b11, kb_base + (uint32_t)(g*16*ASTR)*2 + kk*32);
                mma16816(s[2*g],   a0,a1,a2,a3, b00,b01);
                mma16816(s[2*g+1], a0,a1,a2,a3, b10,b11);
            }
        }

        // ---- online softmax ----
        float alpha[2];
        #pragma unroll
        for (int h = 0; h < 2; h++) {
            float mx = -1e30f;
            #pragma unroll
            for (int j = 0; j < 8; j++) mx = fmaxf(mx, fmaxf(s[j][2*h], s[j][2*h+1]));
            mx = fmaxf(mx, __shfl_xor_sync(0xffffffffu, mx, 1));
            mx = fmaxf(mx, __shfl_xor_sync(0xffffffffu, mx, 2));
            float mn = fmaxf(mrow[h], mx);
            float al = __expf(mrow[h] - mn);
            mrow[h] = mn;
            float rs = 0.f;
            #pragma unroll
            for (int j = 0; j < 8; j++) {
                float p0 = __expf(s[j][2*h]   - mn);
                float p1 = __expf(s[j][2*h+1] - mn);
                s[j][2*h] = p0; s[j][2*h+1] = p1;
                rs += p0 + p1;
            }
            rs += __shfl_xor_sync(0xffffffffu, rs, 1);
            rs += __shfl_xor_sync(0xffffffffu, rs, 2);
            lrow[h] = lrow[h]*al + rs;
            alpha[h] = al;
        }
        #pragma unroll
        for (int j = 0; j < 32; j++) {
            o[j][0] *= alpha[0]; o[j][1] *= alpha[0];
            o[j][2] *= alpha[1]; o[j][3] *= alpha[1];
        }

        // ---- O += P @ V ----
        #pragma unroll
        for (int ks2 = 0; ks2 < 4; ks2++) {
            uint32_t a0 = cvt2(s[2*ks2][1],   s[2*ks2][0]);
            uint32_t a1 = cvt2(s[2*ks2][3],   s[2*ks2][2]);
            uint32_t a2 = cvt2(s[2*ks2+1][1], s[2*ks2+1][0]);
            uint32_t a3 = cvt2(s[2*ks2+1][3], s[2*ks2+1][2]);
            #pragma unroll
            for (int g = 0; g < 16; g++) {
                uint32_t b00,b01,b10,b11;
                ldm4t(b00,b01,b10,b11, vb_base + (uint32_t)(ks2*16*ASTR + g*16)*2);
                mma16816(o[2*g],   a0,a1,a2,a3, b00,b01);
                mma16816(o[2*g+1], a0,a1,a2,a3, b10,b11);
            }
        }
        __syncthreads();
    }

    // ---- epilogue: normalize, write g_a (n, c) bf16 ----
    __nv_bfloat16* ab = g_a + (size_t)b*HW*CC;
    int qr = lane >> 2, qc = (lane & 3) << 1;
    #pragma unroll
    for (int h = 0; h < 2; h++) {
        float inv = 1.0f / lrow[h];
        int row = n0 + r0 + qr + 8*h;
        #pragma unroll
        for (int j = 0; j < 32; j++) {
            uint32_t r = cvt2(o[j][2*h+1]*inv, o[j][2*h]*inv);
            *reinterpret_cast<uint32_t*>(&ab[(size_t)row*CC + 8*j + qc]) = r;
        }
    }
}

// ============================================================
// Output projection + residual, bf16 tensor-core GEMM, fp32 out:
// out[b,o,s] = x[b,o,s] + bp[o] + sum_c wp[o,c] * A[b,s,c]
// M=o(64), N=s(128): A=W non-trans, B=Astrip non-trans.
// ============================================================
#define PSTR2 264

__global__ void __launch_bounds__(256) outproj_tc_kernel(const float* __restrict__ bias,
                                                         const float* __restrict__ x,
                                                         float* __restrict__ outp) {
    int b  = blockIdx.z;
    int s0 = blockIdx.x << 7;
    int o0 = blockIdx.y << 6;
    const __nv_bfloat16* Ab = g_a + (size_t)b*HW*CC;

    extern __shared__ __nv_bfloat16 smp[];
    __nv_bfloat16* As = smp;               // 128 x PSTR2 (s rows, c cols)
    __nv_bfloat16* Ws = smp + 128*PSTR2;   // 64 x WSTR

    int tid = threadIdx.x, lane = tid & 31, warp = tid >> 5;
    int l8 = lane & 7;

    for (int l = tid; l < 4096; l += 256) {
        int row = l >> 5, col = (l & 31) << 3;
        *reinterpret_cast<uint4*>(&As[row*PSTR2 + col]) =
            *reinterpret_cast<const uint4*>(&Ab[(size_t)(s0+row)*CC + col]);
    }
    for (int l = tid; l < 2048; l += 256) {
        int row = l >> 5, col = (l & 31) << 3;
        *reinterpret_cast<uint4*>(&Ws[row*WSTR + col]) =
            *reinterpret_cast<const uint4*>(&g_wp[(o0+row)*CC + col]);
    }
    __syncthreads();

    uint32_t Asa = s2u(As), Wsa = s2u(Ws);
    int warp_o = warp >> 1, warp_s = warp & 1;
    uint32_t a_base = Wsa + (uint32_t)((warp_o*16 + l8 + ((lane>>3)&1)*8)*WSTR + (lane>>4)*8) * 2;
    uint32_t b_base = Asa + (uint32_t)((warp_s*64 + ((lane>>4)&1)*8 + l8)*PSTR2 + ((lane>>3)&1)*8) * 2;

    float acc[8][4];
    #pragma unroll
    for (int j = 0; j < 8; j++) { acc[j][0]=acc[j][1]=acc[j][2]=acc[j][3]=0.f; }

    #pragma unroll 4
    for (int kk = 0; kk < 16; kk++) {
        uint32_t a0,a1,a2,a3;
        ldm4(a0,a1,a2,a3, a_base + kk*32);
        #pragma unroll
        for (int g = 0; g < 4; g++) {
            uint32_t b00,b01,b10,b11;
            ldm4(b00,b01,b10,b11, b_base + (uint32_t)(g*16*PSTR2)*2 + kk*32);
            mma16816(acc[2*g],   a0,a1,a2,a3, b00,b01);
            mma16816(acc[2*g+1], a0,a1,a2,a3, b10,b11);
        }
    }

    const float* xb = x + (size_t)b*CC*HW;
    float* ob = outp + (size_t)b*CC*HW;
    int qr = lane >> 2, qc = (lane & 3) << 1;
    #pragma unroll
    for (int h = 0; h < 2; h++) {
        int o_r = o0 + warp_o*16 + qr + 8*h;
        float bv = bias[o_r];
        #pragma unroll
        for (int j = 0; j < 8; j++) {
            int s_c = s0 + warp_s*64 + j*8 + qc;
            size_t idx = (size_t)o_r*HW + s_c;
            float2 xv = *reinterpret_cast<const float2*>(&xb[idx]);
            float2 r = make_float2(acc[j][2*h] + bv + xv.x, acc[j][2*h+1] + bv + xv.y);
            *reinterpret_cast<float2*>(&ob[idx]) = r;
        }
    }
}

// ============================================================
extern "C" void kernel_launch(void* const* d_in, const int* in_sizes, int n_in,
                              void* d_out, int out_size) {
    const float* x    = (const float*)d_in[0];
    const float* gn_w = (const float*)d_in[1];
    const float* gn_b = (const float*)d_in[2];
    const float* wq   = (const float*)d_in[3];
    const float* bq   = (const float*)d_in[4];
    const float* wk   = (const float*)d_in[5];
    const float* bk   = (const float*)d_in[6];
    const float* wv   = (const float*)d_in[7];
    const float* bv   = (const float*)d_in[8];
    const float* wp   = (const float*)d_in[9];
    const float* bp   = (const float*)d_in[10];
    float* out = (float*)d_out;

    const int attn_smem = (128 + 4*64) * ASTR * 2;            // 202,752 B
    const int proj_smem = (256*HSTR + 64*WSTR) * 2;           // 103,424 B
    const int outp_smem = (128*PSTR2 + 64*WSTR) * 2;          // 101,376 B
    cudaFuncSetAttribute(attn_kernel, cudaFuncAttributeMaxDynamicSharedMemorySize, attn_smem);
    cudaFuncSetAttribute(proj_tc_kernel<0>, cudaFuncAttributeMaxDynamicSharedMemorySize, proj_smem);
    cudaFuncSetAttribute(proj_tc_kernel<1>, cudaFuncAttributeMaxDynamicSharedMemorySize, proj_smem);
    cudaFuncSetAttribute(proj_tc_kernel<2>, cudaFuncAttributeMaxDynamicSharedMemorySize, proj_smem);
    cudaFuncSetAttribute(outproj_tc_kernel, cudaFuncAttributeMaxDynamicSharedMemorySize, outp_smem);

    wconv_kernel<<<256, 256>>>(wq, wk, wv, wp);
    gn_kernel<<<128, 256>>>(x, gn_w, gn_b);

    dim3 pg(32, 4, BB);
    proj_tc_kernel<0><<<pg, 256, proj_smem>>>(bq);
    proj_tc_kernel<1><<<pg, 256, proj_smem>>>(bk);
    proj_tc_kernel<2><<<pg, 256, proj_smem>>>(bv);

    dim3 ag(32, BB);
    attn_kernel<<<ag, 256, attn_smem>>>();

    outproj_tc_kernel<<<pg, 256, outp_smem>>>(bp, x, out);
}

// round 11
// speedup vs baseline: 1.0500x; 1.0500x over previous
#include <cuda_runtime.h>
#include <cuda_bf16.h>
#include <cstdint>

#define HW 4096
#define CC 256
#define BB 4

// ---- scratch (static device arrays; no allocation allowed) ----
__device__ __align__(16) __nv_bfloat16 g_h [BB*CC*HW];   // groupnorm out (b,c,s)
__device__ __align__(16) __nv_bfloat16 g_q [BB*CC*HW];   // q flat, pre-scaled C^-0.5
__device__ __align__(16) __nv_bfloat16 g_kt[BB*HW*CC];   // k transposed (b,m,c)
__device__ __align__(16) __nv_bfloat16 g_v [BB*CC*HW];   // v conv out flat
__device__ __align__(16) __nv_bfloat16 g_a [BB*HW*CC];   // attn out (b,n,c)

// ============ groupnorm: 128 blocks x 512 threads, float4 both passes ============
__global__ void __launch_bounds__(512) gn_kernel(const float* __restrict__ x,
                                                 const float* __restrict__ gw,
                                                 const float* __restrict__ gb) {
    int b = blockIdx.x >> 5, g = blockIdx.x & 31;
    const float* xp = x   + ((size_t)b*CC + g*8) * HW;
    __nv_bfloat16* hp = g_h + ((size_t)b*CC + g*8) * HW;
    int tid = threadIdx.x;

    float s = 0.f, ss = 0.f;
    const float4* xv4 = reinterpret_cast<const float4*>(xp);
    for (int i = tid; i < 8*HW/4; i += 512) {
        float4 v = xv4[i];
        s  += v.x + v.y + v.z + v.w;
        ss += v.x*v.x + v.y*v.y + v.z*v.z + v.w*v.w;
    }
    __shared__ float red0[16], red1[16];
    #pragma unroll
    for (int off = 16; off; off >>= 1) {
        s  += __shfl_xor_sync(0xffffffffu, s,  off);
        ss += __shfl_xor_sync(0xffffffffu, ss, off);
    }
    if ((tid & 31) == 0) { red0[tid>>5] = s; red1[tid>>5] = ss; }
    __syncthreads();
    __shared__ float mu_s, rstd_s;
    if (tid == 0) {
        float S = 0.f, SS = 0.f;
        #pragma unroll
        for (int i = 0; i < 16; i++) { S += red0[i]; SS += red1[i]; }
        float inv = 1.0f / (8.0f*HW);
        float mu = S * inv, var = SS * inv - mu*mu;
        mu_s = mu; rstd_s = rsqrtf(var + 1e-5f);
    }
    __syncthreads();
    float mu = mu_s, rstd = rstd_s;
    for (int i = tid; i < 8*HW/4; i += 512) {
        int c = g*8 + (i >> 10);               // 1024 float4 per channel
        float a = gw[c]*rstd, bb2 = gb[c] - mu*a;
        float4 v = xv4[i];
        __nv_bfloat162 r0 = __floats2bfloat162_rn(v.x*a + bb2, v.y*a + bb2);
        __nv_bfloat162 r1 = __floats2bfloat162_rn(v.z*a + bb2, v.w*a + bb2);
        uint2 pk;
        pk.x = *reinterpret_cast<uint32_t*>(&r0);
        pk.y = *reinterpret_cast<uint32_t*>(&r1);
        *reinterpret_cast<uint2*>(&hp[i*4]) = pk;
    }
}

// ============ helpers ============
__device__ __forceinline__ uint32_t s2u(const void* p) {
    uint32_t a;
    asm("{ .reg .u64 t; cvta.to.shared.u64 t, %1; cvt.u32.u64 %0, t; }" : "=r"(a) : "l"(p));
    return a;
}
__device__ __forceinline__ void ldm4(uint32_t& r0, uint32_t& r1, uint32_t& r2, uint32_t& r3, uint32_t a) {
    asm volatile("ldmatrix.sync.aligned.m8n8.x4.shared.b16 {%0,%1,%2,%3},[%4];"
                 : "=r"(r0), "=r"(r1), "=r"(r2), "=r"(r3) : "r"(a));
}
__device__ __forceinline__ void ldm4t(uint32_t& r0, uint32_t& r1, uint32_t& r2, uint32_t& r3, uint32_t a) {
    asm volatile("ldmatrix.sync.aligned.m8n8.x4.trans.shared.b16 {%0,%1,%2,%3},[%4];"
                 : "=r"(r0), "=r"(r1), "=r"(r2), "=r"(r3) : "r"(a));
}
__device__ __forceinline__ void mma16816(float* d, uint32_t a0, uint32_t a1, uint32_t a2, uint32_t a3,
                                         uint32_t b0, uint32_t b1) {
    asm volatile("mma.sync.aligned.m16n8k16.row.col.f32.bf16.bf16.f32 "
                 "{%0,%1,%2,%3},{%4,%5,%6,%7},{%8,%9},{%0,%1,%2,%3};"
                 : "+f"(d[0]), "+f"(d[1]), "+f"(d[2]), "+f"(d[3])
                 : "r"(a0), "r"(a1), "r"(a2), "r"(a3), "r"(b0), "r"(b1));
}
__device__ __forceinline__ uint32_t cvt2(float hi, float lo) {
    uint32_t d; asm("cvt.rn.bf16x2.f32 %0, %1, %2;" : "=r"(d) : "f"(hi), "f"(lo)); return d;
}
__device__ __forceinline__ void cpa16(uint32_t dst, const void* src) {
    asm volatile("cp.async.cg.shared.global [%0], [%1], 16;" :: "r"(dst), "l"(src));
}

// ============ fused q/k/v projection (H strip loaded once, W converted inline) ============
#define HSTR 136
#define WSTR 264

__global__ void __launch_bounds__(256) qkv_kernel(const float* __restrict__ wq, const float* __restrict__ bq,
                                                  const float* __restrict__ wk, const float* __restrict__ bk,
                                                  const float* __restrict__ wv, const float* __restrict__ bvv) {
    int b  = blockIdx.y;
    int s0 = blockIdx.x << 7;
    const __nv_bfloat16* Hb = g_h + (size_t)b*CC*HW;

    extern __shared__ __nv_bfloat16 smp[];
    __nv_bfloat16* Hs = smp;              // 256 x HSTR
    __nv_bfloat16* Ws = smp + 256*HSTR;   // 64 x WSTR

    int tid = threadIdx.x, lane = tid & 31, warp = tid >> 5;
    int l8 = lane & 7;
    int qr = lane >> 2, qc = (lane & 3) << 1;

    for (int l = tid; l < 4096; l += 256) {
        int row = l >> 4, col = (l & 15) << 3;
        *reinterpret_cast<uint4*>(&Hs[row*HSTR + col]) =
            *reinterpret_cast<const uint4*>(&Hb[(size_t)row*HW + s0 + col]);
    }
    uint32_t Hsa = s2u(Hs), Wsa = s2u(Ws);

    for (int mat = 0; mat < 3; mat++) {
        const float* Wb  = (mat == 0) ? wq : (mat == 1) ? wk : wv;
        const float* bias = (mat == 0) ? bq : (mat == 1) ? bk : bvv;
        for (int ob = 0; ob < 4; ob++) {
            int o0 = ob << 6;
            __syncthreads();
            // load + convert W tile fp32 -> bf16 smem
            for (int l = tid; l < 2048; l += 256) {
                int row = l >> 5, col = (l & 31) << 3;
                const float4* wsrc = reinterpret_cast<const float4*>(&Wb[(size_t)(o0+row)*CC + col]);
                float4 a = wsrc[0], c = wsrc[1];
                uint4 pk;
                pk.x = cvt2(a.y, a.x); pk.y = cvt2(a.w, a.z);
                pk.z = cvt2(c.y, c.x); pk.w = cvt2(c.w, c.z);
                *reinterpret_cast<uint4*>(&Ws[row*WSTR + col]) = pk;
            }
            __syncthreads();
            float acc[8][4];
            #pragma unroll
            for (int j = 0; j < 8; j++) { acc[j][0]=acc[j][1]=acc[j][2]=acc[j][3]=0.f; }
            if (mat != 1) {
                // out[o,s]: A=W, B=H(trans). warp: 16o x 64s
                int warp_o = warp >> 1, warp_s = warp & 1;
                uint32_t a_base = Wsa + (uint32_t)((warp_o*16 + l8 + ((lane>>3)&1)*8)*WSTR + (lane>>4)*8) * 2;
                uint32_t b_base = Hsa + (uint32_t)((l8 + ((lane>>3)&1)*8)*HSTR + warp_s*64 + (lane>>4)*8) * 2;
                #pragma unroll 4
                for (int kk = 0; kk < 16; kk++) {
                    uint32_t a0,a1,a2,a3;
                    ldm4(a0,a1,a2,a3, a_base + kk*32);
                    #pragma unroll
                    for (int g = 0; g < 4; g++) {
                        uint32_t b00,b01,b10,b11;
                        ldm4t(b00,b01,b10,b11, b_base + (uint32_t)(kk*16*HSTR + g*16)*2);
                        mma16816(acc[2*g],   a0,a1,a2,a3, b00,b01);
                        mma16816(acc[2*g+1], a0,a1,a2,a3, b10,b11);
                    }
                }
                const float scale = (mat == 0) ? 0.0625f : 1.0f;
                __nv_bfloat16* ob2 = (mat == 0 ? g_q : g_v) + (size_t)b*CC*HW;
                #pragma unroll
                for (int h = 0; h < 2; h++) {
                    int o_r = o0 + warp_o*16 + qr + 8*h;
                    float bvl = bias[o_r];
                    #pragma unroll
                    for (int j = 0; j < 8; j++) {
                        int s_c = s0 + warp_s*64 + j*8 + qc;
                        uint32_t r = cvt2((acc[j][2*h+1]+bvl)*scale, (acc[j][2*h]+bvl)*scale);
                        *reinterpret_cast<uint32_t*>(&ob2[(size_t)o_r*HW + s_c]) = r;
                    }
                }
            } else {
                // out[s,o]: A=H(trans-A), B=W. warp: 16s x 64o
                uint32_t a_base = Hsa + (uint32_t)((l8 + ((lane>>4)&1)*8)*HSTR + warp*16 + ((lane>>3)&1)*8) * 2;
                uint32_t b_base = Wsa + (uint32_t)((((lane>>4)&1)*8 + l8)*WSTR + ((lane>>3)&1)*8) * 2;
                #pragma unroll 4
                for (int kk = 0; kk < 16; kk++) {
                    uint32_t a0,a1,a2,a3;
                    ldm4t(a0,a1,a2,a3, a_base + (uint32_t)(kk*16*HSTR)*2);
                    #pragma unroll
                    for (int g = 0; g < 4; g++) {
                        uint32_t b00,b01,b10,b11;
                        ldm4(b00,b01,b10,b11, b_base + (uint32_t)(g*16*WSTR)*2 + kk*32);
                        mma16816(acc[2*g],   a0,a1,a2,a3, b00,b01);
                        mma16816(acc[2*g+1], a0,a1,a2,a3, b10,b11);
                    }
                }
                __nv_bfloat16* ob2 = g_kt + (size_t)b*HW*CC;
                #pragma unroll
                for (int h = 0; h < 2; h++) {
                    int s_r = s0 + warp*16 + qr + 8*h;
                    #pragma unroll
                    for (int j = 0; j < 8; j++) {
                        int o_c = o0 + j*8 + qc;
                        uint32_t r = cvt2(acc[j][2*h+1]+bias[o_c+1], acc[j][2*h]+bias[o_c]);
                        *reinterpret_cast<uint32_t*>(&ob2[(size_t)s_r*CC + o_c]) = r;
                    }
                }
            }
        }
    }
}

// ============ flash attention, bf16 mma.sync, cp.async double-buffered K/V ============
#define ASTR 264

__global__ void __launch_bounds__(256, 1) attn_kernel() {
    int b  = blockIdx.y;
    int n0 = blockIdx.x << 7;
    const __nv_bfloat16* qf = g_q  + (size_t)b*CC*HW;
    const __nv_bfloat16* kf = g_kt + (size_t)b*HW*CC;
    const __nv_bfloat16* vf = g_v  + (size_t)b*CC*HW;

    extern __shared__ __nv_bfloat16 sm[];
    __nv_bfloat16* Qs = sm;                         // 128 x ASTR
    __nv_bfloat16* Kb[2] = { Qs + 128*ASTR, Qs + 192*ASTR };
    __nv_bfloat16* Vb[2] = { Qs + 256*ASTR, Qs + 320*ASTR };

    int tid  = threadIdx.x;
    int lane = tid & 31, warp = tid >> 5;
    int r0 = warp << 4;
    int l8 = lane & 7;

    {
        const uint4* src = reinterpret_cast<const uint4*>(qf + (size_t)n0*CC);
        for (int l = tid; l < 4096; l += 256) {
            int row = l >> 5, col = (l & 31) << 3;
            *reinterpret_cast<uint4*>(&Qs[row*ASTR + col]) = src[l];
        }
    }
    {
        uint32_t Kd = s2u(Kb[0]), Vd = s2u(Vb[0]);
        const uint4* ks = reinterpret_cast<const uint4*>(kf);
        const uint4* vs = reinterpret_cast<const uint4*>(vf);
        for (int l = tid; l < 2048; l += 256) {
            int row = l >> 5; uint32_t off = ((row*ASTR) + ((l & 31) << 3)) * 2;
            cpa16(Kd + off, &ks[l]);
            cpa16(Vd + off, &vs[l]);
        }
        asm volatile("cp.async.commit_group;");
    }

    uint32_t Qsa = s2u(Qs);
    uint32_t a_base = Qsa + ((r0 + l8 + ((lane >> 3) & 1)*8)*ASTR + (lane >> 4)*8) * 2;
    uint32_t kb_pat = (uint32_t)((((lane >> 4) & 1)*8 + l8)*ASTR + ((lane >> 3) & 1)*8) * 2;
    uint32_t vb_pat = (uint32_t)((((lane >> 3) & 1)*8 + l8)*ASTR + (lane >> 4)*8) * 2;

    float s[8][4];
    float o[32][4];
    #pragma unroll
    for (int j = 0; j < 32; j++) { o[j][0]=o[j][1]=o[j][2]=o[j][3]=0.f; }
    float mrow[2] = {-1e30f, -1e30f};
    float lrow[2] = {0.f, 0.f};

    for (int t = 0; t < 64; t++) {
        if (t + 1 < 64) {
            int nb = (t + 1) & 1;
            uint32_t Kd = s2u(Kb[nb]), Vd = s2u(Vb[nb]);
            const uint4* ks = reinterpret_cast<const uint4*>(kf + (size_t)(t+1)*64*CC);
            const uint4* vs = reinterpret_cast<const uint4*>(vf + (size_t)(t+1)*64*CC);
            for (int l = tid; l < 2048; l += 256) {
                int row = l >> 5; uint32_t off = ((row*ASTR) + ((l & 31) << 3)) * 2;
                cpa16(Kd + off, &ks[l]);
                cpa16(Vd + off, &vs[l]);
            }
            asm volatile("cp.async.commit_group;");
            asm volatile("cp.async.wait_group 1;");
        } else {
            asm volatile("cp.async.wait_group 0;");
        }
        __syncthreads();

        uint32_t Ksa = s2u(Kb[t & 1]), Vsa = s2u(Vb[t & 1]);
        uint32_t kb_base = Ksa + kb_pat;
        uint32_t vb_base = Vsa + vb_pat;

        #pragma unroll
        for (int j = 0; j < 8; j++) { s[j][0]=s[j][1]=s[j][2]=s[j][3]=0.f; }
        #pragma unroll 4
        for (int kk = 0; kk < 16; kk++) {
            uint32_t a0,a1,a2,a3;
            ldm4(a0,a1,a2,a3, a_base + kk*32);
            #pragma unroll
            for (int g = 0; g < 4; g++) {
                uint32_t b00,b01,b10,b11;
                ldm4(b00,b01,b10,b11, kb_base + (uint32_t)(g*16*ASTR)*2 + kk*32);
                mma16816(s[2*g],   a0,a1,a2,a3, b00,b01);
                mma16816(s[2*g+1], a0,a1,a2,a3, b10,b11);
            }
        }

        float alpha[2];
        #pragma unroll
        for (int h = 0; h < 2; h++) {
            float mx = -1e30f;
            #pragma unroll
            for (int j = 0; j < 8; j++) mx = fmaxf(mx, fmaxf(s[j][2*h], s[j][2*h+1]));
            mx = fmaxf(mx, __shfl_xor_sync(0xffffffffu, mx, 1));
            mx = fmaxf(mx, __shfl_xor_sync(0xffffffffu, mx, 2));
            float mn = fmaxf(mrow[h], mx);
            float al = __expf(mrow[h] - mn);
            mrow[h] = mn;
            float rs = 0.f;
            #pragma unroll
            for (int j = 0; j < 8; j++) {
                float p0 = __expf(s[j][2*h]   - mn);
                float p1 = __expf(s[j][2*h+1] - mn);
                s[j][2*h] = p0; s[j][2*h+1] = p1;
                rs += p0 + p1;
            }
            rs += __shfl_xor_sync(0xffffffffu, rs, 1);
            rs += __shfl_xor_sync(0xffffffffu, rs, 2);
            lrow[h] = lrow[h]*al + rs;
            alpha[h] = al;
        }
        #pragma unroll
        for (int j = 0; j < 32; j++) {
            o[j][0] *= alpha[0]; o[j][1] *= alpha[0];
            o[j][2] *= alpha[1]; o[j][3] *= alpha[1];
        }

        #pragma unroll
        for (int ks2 = 0; ks2 < 4; ks2++) {
            uint32_t a0 = cvt2(s[2*ks2][1],   s[2*ks2][0]);
            uint32_t a1 = cvt2(s[2*ks2][3],   s[2*ks2][2]);
            uint32_t a2 = cvt2(s[2*ks2+1][1], s[2*ks2+1][0]);
            uint32_t a3 = cvt2(s[2*ks2+1][3], s[2*ks2+1][2]);
            #pragma unroll
            for (int g = 0; g < 16; g++) {
                uint32_t b00,b01,b10,b11;
                ldm4t(b00,b01,b10,b11, vb_base + (uint32_t)(ks2*16*ASTR + g*16)*2);
                mma16816(o[2*g],   a0,a1,a2,a3, b00,b01);
                mma16816(o[2*g+1], a0,a1,a2,a3, b10,b11);
            }
        }
        __syncthreads();
    }

    __nv_bfloat16* ab = g_a + (size_t)b*HW*CC;
    int qr = lane >> 2, qc = (lane & 3) << 1;
    #pragma unroll
    for (int h = 0; h < 2; h++) {
        float inv = 1.0f / lrow[h];
        int row = n0 + r0 + qr + 8*h;
        #pragma unroll
        for (int j = 0; j < 32; j++) {
            uint32_t r = cvt2(o[j][2*h+1]*inv, o[j][2*h]*inv);
            *reinterpret_cast<uint32_t*>(&ab[(size_t)row*CC + 8*j + qc]) = r;
        }
    }
}

// ============ output projection + residual (wp converted inline) ============
#define PSTR2 264
__global__ void __launch_bounds__(256) outproj_tc_kernel(const float* __restrict__ wp,
                                                         const float* __restrict__ bias,
                                                         const float* __restrict__ x,
                                                         float* __restrict__ outp) {
    int b  = blockIdx.z;
    int s0 = blockIdx.x << 7;
    int o0 = blockIdx.y << 6;
    const __nv_bfloat16* Ab = g_a + (size_t)b*HW*CC;

    extern __shared__ __nv_bfloat16 smp[];
    __nv_bfloat16* As = smp;               // 128 x PSTR2
    __nv_bfloat16* Ws = smp + 128*PSTR2;   // 64 x WSTR

    int tid = threadIdx.x, lane = tid & 31, warp = tid >> 5;
    int l8 = lane & 7;

    for (int l = tid; l < 4096; l += 256) {
        int row = l >> 5, col = (l & 31) << 3;
        *reinterpret_cast<uint4*>(&As[row*PSTR2 + col]) =
            *reinterpret_cast<const uint4*>(&Ab[(size_t)(s0+row)*CC + col]);
    }
    for (int l = tid; l < 2048; l += 256) {
        int row = l >> 5, col = (l & 31) << 3;
        const float4* wsrc = reinterpret_cast<const float4*>(&wp[(size_t)(o0+row)*CC + col]);
        float4 a = wsrc[0], c = wsrc[1];
        uint4 pk;
        pk.x = cvt2(a.y, a.x); pk.y = cvt2(a.w, a.z);
        pk.z = cvt2(c.y, c.x); pk.w = cvt2(c.w, c.z);
        *reinterpret_cast<uint4*>(&Ws[row*WSTR + col]) = pk;
    }
    __syncthreads();

    uint32_t Asa = s2u(As), Wsa = s2u(Ws);
    int warp_o = warp >> 1, warp_s = warp & 1;
    uint32_t a_base = Wsa + (uint32_t)((warp_o*16 + l8 + ((lane>>3)&1)*8)*WSTR + (lane>>4)*8) * 2;
    uint32_t b_base = Asa + (uint32_t)((warp_s*64 + ((lane>>4)&1)*8 + l8)*PSTR2 + ((lane>>3)&1)*8) * 2;

    float acc[8][4];
    #pragma unroll
    for (int j = 0; j < 8; j++) { acc[j][0]=acc[j][1]=acc[j][2]=acc[j][3]=0.f; }
    #pragma unroll 4
    for (int kk = 0; kk < 16; kk++) {
        uint32_t a0,a1,a2,a3;
        ldm4(a0,a1,a2,a3, a_base + kk*32);
        #pragma unroll
        for (int g = 0; g < 4; g++) {
            uint32_t b00,b01,b10,b11;
            ldm4(b00,b01,b10,b11, b_base + (uint32_t)(g*16*PSTR2)*2 + kk*32);
            mma16816(acc[2*g],   a0,a1,a2,a3, b00,b01);
            mma16816(acc[2*g+1], a0,a1,a2,a3, b10,b11);
        }
    }

    const float* xb = x + (size_t)b*CC*HW;
    float* ob = outp + (size_t)b*CC*HW;
    int qr = lane >> 2, qc = (lane & 3) << 1;
    #pragma unroll
    for (int h = 0; h < 2; h++) {
        int o_r = o0 + warp_o*16 + qr + 8*h;
        float bv = bias[o_r];
        #pragma unroll
        for (int j = 0; j < 8; j++) {
            int s_c = s0 + warp_s*64 + j*8 + qc;
            size_t idx = (size_t)o_r*HW + s_c;
            float2 xv = *reinterpret_cast<const float2*>(&xb[idx]);
            float2 r = make_float2(acc[j][2*h] + bv + xv.x, acc[j][2*h+1] + bv + xv.y);
            *reinterpret_cast<float2*>(&ob[idx]) = r;
        }
    }
}

// ============================================================
extern "C" void kernel_launch(void* const* d_in, const int* in_sizes, int n_in,
                              void* d_out, int out_size) {
    const float* x    = (const float*)d_in[0];
    const float* gn_w = (const float*)d_in[1];
    const float* gn_b = (const float*)d_in[2];
    const float* wq   = (const float*)d_in[3];
    const float* bq   = (const float*)d_in[4];
    const float* wk   = (const float*)d_in[5];
    const float* bk   = (const float*)d_in[6];
    const float* wv   = (const float*)d_in[7];
    const float* bv   = (const float*)d_in[8];
    const float* wp   = (const float*)d_in[9];
    const float* bp   = (const float*)d_in[10];
    float* out = (float*)d_out;

    const int attn_smem = (128 + 4*64) * ASTR * 2;            // 202,752 B
    const int qkv_smem  = (256*HSTR + 64*WSTR) * 2;           // 103,424 B
    const int outp_smem = (128*PSTR2 + 64*WSTR) * 2;          // 101,376 B
    cudaFuncSetAttribute(attn_kernel, cudaFuncAttributeMaxDynamicSharedMemorySize, attn_smem);
    cudaFuncSetAttribute(qkv_kernel, cudaFuncAttributeMaxDynamicSharedMemorySize, qkv_smem);
    cudaFuncSetAttribute(outproj_tc_kernel, cudaFuncAttributeMaxDynamicSharedMemorySize, outp_smem);

    gn_kernel<<<128, 512>>>(x, gn_w, gn_b);

    dim3 qg(32, BB);
    qkv_kernel<<<qg, 256, qkv_smem>>>(wq, bq, wk, bk, wv, bv);

    dim3 ag(32, BB);
    attn_kernel<<<ag, 256, attn_smem>>>();

    dim3 pg(32, 4, BB);
    outproj_tc_kernel<<<pg, 256, outp_smem>>>(wp, bp, x, out);
}